// round 1
// baseline (speedup 1.0000x reference)
#include <cuda_runtime.h>
#include <math.h>

#define L_SEQ 2048
#define DM    1024
#define DI    2048   // d_inner
#define DS    16     // d_state
#define DTR   64     // dt_rank
#define XDBL  96     // dt_rank + 2*d_state

// Scratch (no allocation allowed in kernel_launch; use device globals)
__device__ float g_xz[L_SEQ * 2 * DI];   // in-proj output: [:, :DI]=xs_raw, [:, DI:]=z
__device__ float g_xs[L_SEQ * DI];       // conv+silu output
__device__ float g_xdbl[L_SEQ * XDBL];   // [dt_in | B | C]
__device__ float g_dt[L_SEQ * DI];       // softplus(dt_in @ W_dt^T + b_dt)
__device__ float g_y[L_SEQ * DI];        // (scan_y + xs*D) * silu(z)

// ---------------------------------------------------------------------------
// GEMM: C[m][n] = sum_k A[m*lda+k] * B[n*ldb+k]   (both row-major, K-contig)
// optional epilogue: softplus(acc + bias[n])
// 64x64 tile, 256 threads, 4x4 per thread, k-major smem tiles.
// ---------------------------------------------------------------------------
template<bool SOFTPLUS>
__global__ void __launch_bounds__(256) gemm_tn(
    const float* __restrict__ A, const float* __restrict__ B,
    const float* __restrict__ bias, float* __restrict__ C,
    int M, int N, int K, int lda, int ldb, int ldc)
{
    __shared__ float As[16][68];
    __shared__ float Bs[16][68];
    const int tid = threadIdx.x;
    const int tx = tid & 15, ty = tid >> 4;
    const int m0 = blockIdx.y * 64, n0 = blockIdx.x * 64;
    // loader: thread -> (row lr in [0,64), k-offset lk in {0,4,8,12})
    const int lr = tid >> 2;
    const int lk = (tid & 3) << 2;

    float acc[4][4] = {};

    const bool am = (m0 + lr) < M;
    const bool bm = (n0 + lr) < N;
    const float* Aptr = A + (size_t)(m0 + lr) * lda + lk;
    const float* Bptr = B + (size_t)(n0 + lr) * ldb + lk;

    for (int k0 = 0; k0 < K; k0 += 16) {
        float4 av = make_float4(0.f, 0.f, 0.f, 0.f);
        float4 bv = make_float4(0.f, 0.f, 0.f, 0.f);
        if (am) av = *(const float4*)(Aptr + k0);
        if (bm) bv = *(const float4*)(Bptr + k0);
        __syncthreads();
        As[lk + 0][lr] = av.x; As[lk + 1][lr] = av.y;
        As[lk + 2][lr] = av.z; As[lk + 3][lr] = av.w;
        Bs[lk + 0][lr] = bv.x; Bs[lk + 1][lr] = bv.y;
        Bs[lk + 2][lr] = bv.z; Bs[lk + 3][lr] = bv.w;
        __syncthreads();
#pragma unroll
        for (int kk = 0; kk < 16; ++kk) {
            float4 af = *(const float4*)&As[kk][ty << 2];
            float4 bf = *(const float4*)&Bs[kk][tx << 2];
            float aa[4] = {af.x, af.y, af.z, af.w};
            float bb[4] = {bf.x, bf.y, bf.z, bf.w};
#pragma unroll
            for (int i = 0; i < 4; ++i)
#pragma unroll
                for (int j = 0; j < 4; ++j)
                    acc[i][j] = fmaf(aa[i], bb[j], acc[i][j]);
        }
    }

#pragma unroll
    for (int i = 0; i < 4; ++i) {
        int m = m0 + (ty << 2) + i;
        if (m >= M) continue;
#pragma unroll
        for (int j = 0; j < 4; ++j) {
            int n = n0 + (tx << 2) + j;
            if (n >= N) continue;
            float v = acc[i][j];
            if (SOFTPLUS) {
                v += bias[n];
                v = (v > 20.f) ? v : log1pf(expf(v));
            }
            C[(size_t)m * ldc + n] = v;
        }
    }
}

// ---------------------------------------------------------------------------
// Depthwise causal conv (4-tap) + SiLU.  Reads xs_raw from g_xz[:, :DI].
// ---------------------------------------------------------------------------
__global__ void conv_silu_kernel(const float* __restrict__ cw,
                                 const float* __restrict__ cb)
{
    int idx = blockIdx.x * blockDim.x + threadIdx.x;
    if (idx >= L_SEQ * DI) return;
    int l = idx / DI, d = idx % DI;
    float acc = cb[d];
#pragma unroll
    for (int t = 0; t < 4; ++t) {
        int ll = l - 3 + t;
        if (ll >= 0) acc = fmaf(cw[d * 4 + t], g_xz[(size_t)ll * (2 * DI) + d], acc);
    }
    g_xs[idx] = acc / (1.f + __expf(-acc));  // silu
}

// ---------------------------------------------------------------------------
// Selective scan. 16 lanes per channel (one per state), shfl-xor reduction.
// Also fuses +xs*D and *silu(z) into the output.
// ---------------------------------------------------------------------------
__global__ void __launch_bounds__(256) scan_kernel(
    const float* __restrict__ A_log, const float* __restrict__ Dp)
{
    const int d = blockIdx.x * 16 + (threadIdx.x >> 4);
    const int n = threadIdx.x & 15;
    const float a  = -__expf(A_log[d * DS + n]);
    const float Dd = Dp[d];
    float h = 0.f;
#pragma unroll 2
    for (int l = 0; l < L_SEQ; ++l) {
        float dt = g_dt[(size_t)l * DI + d];
        float xv = g_xs[(size_t)l * DI + d];
        float b  = g_xdbl[l * XDBL + DTR + n];
        float c  = g_xdbl[l * XDBL + DTR + DS + n];
        float dA = __expf(dt * a);
        h = fmaf(dA, h, dt * b * xv);
        float p = h * c;
        p += __shfl_xor_sync(0xffffffffu, p, 1);
        p += __shfl_xor_sync(0xffffffffu, p, 2);
        p += __shfl_xor_sync(0xffffffffu, p, 4);
        p += __shfl_xor_sync(0xffffffffu, p, 8);
        if (n == 0) {
            float z  = g_xz[(size_t)l * (2 * DI) + DI + d];
            float sz = z / (1.f + __expf(-z));
            g_y[(size_t)l * DI + d] = (p + xv * Dd) * sz;
        }
    }
}

// ---------------------------------------------------------------------------
extern "C" void kernel_launch(void* const* d_in, const int* in_sizes, int n_in,
                              void* d_out, int out_size)
{
    const float* x     = (const float*)d_in[0];
    const float* W_in  = (const float*)d_in[1];
    const float* cw    = (const float*)d_in[2];
    const float* cb    = (const float*)d_in[3];
    const float* W_x   = (const float*)d_in[4];
    const float* W_dt  = (const float*)d_in[5];
    const float* b_dt  = (const float*)d_in[6];
    const float* A_log = (const float*)d_in[7];
    const float* Dp    = (const float*)d_in[8];
    const float* W_out = (const float*)d_in[9];
    float* out = (float*)d_out;

    float *xz, *xs, *xdbl, *dt, *y;
    cudaGetSymbolAddress((void**)&xz,   g_xz);
    cudaGetSymbolAddress((void**)&xs,   g_xs);
    cudaGetSymbolAddress((void**)&xdbl, g_xdbl);
    cudaGetSymbolAddress((void**)&dt,   g_dt);
    cudaGetSymbolAddress((void**)&y,    g_y);

    // 1) xz = x @ W_in^T : (2048x1024) * (4096x1024)^T -> (2048x4096)
    gemm_tn<false><<<dim3(4096 / 64, 2048 / 64), 256>>>(
        x, W_in, nullptr, xz, L_SEQ, 2 * DI, DM, DM, DM, 2 * DI);

    // 2) depthwise causal conv + silu -> g_xs
    conv_silu_kernel<<<(L_SEQ * DI + 255) / 256, 256>>>(cw, cb);

    // 3) x_dbl = xs @ W_x^T : (2048x2048) * (96x2048)^T -> (2048x96)
    gemm_tn<false><<<dim3((XDBL + 63) / 64, 2048 / 64), 256>>>(
        xs, W_x, nullptr, xdbl, L_SEQ, XDBL, DI, DI, DI, XDBL);

    // 4) dt = softplus(x_dbl[:, :64] @ W_dt^T + b_dt) : (2048x64)*(2048x64)^T
    gemm_tn<true><<<dim3(DI / 64, 2048 / 64), 256>>>(
        xdbl, W_dt, b_dt, dt, L_SEQ, DI, DTR, XDBL, DTR, DI);

    // 5) selective scan (+ xs*D, * silu(z)) -> g_y
    scan_kernel<<<DI / 16, 256>>>(A_log, Dp);

    // 6) out = y @ W_out^T : (2048x2048) * (1024x2048)^T -> (2048x1024)
    gemm_tn<false><<<dim3(DM / 64, 2048 / 64), 256>>>(
        y, W_out, nullptr, out, L_SEQ, DM, DI, DI, DI, DM);
}

// round 3
// speedup vs baseline: 1.3401x; 1.3401x over previous
#include <cuda_runtime.h>
#include <math.h>
#include <stdint.h>

#define L_SEQ 2048
#define DM    1024
#define DI    2048
#define DS    16
#define DTR   64
#define XDBL  96

__device__ float g_xz[L_SEQ * 2 * DI];
__device__ float g_xs[L_SEQ * DI];
__device__ float g_xdbl[L_SEQ * XDBL];
__device__ float g_dt[L_SEQ * DI];
__device__ float g_y[L_SEQ * DI];

// ---------------------------------------------------------------------------
// helpers
// ---------------------------------------------------------------------------
__device__ __forceinline__ uint32_t f2tf(float x) {
    uint32_t r;
    asm("cvt.rna.tf32.f32 %0, %1;" : "=r"(r) : "f"(x));
    return r;
}
__device__ __forceinline__ void cpasync16(void* smem_ptr, const void* gptr) {
    uint32_t sa = (uint32_t)__cvta_generic_to_shared(smem_ptr);
    asm volatile("cp.async.cg.shared.global [%0], [%1], 16;" :: "r"(sa), "l"(gptr));
}
__device__ __forceinline__ void mma_tf32(float* d, const uint32_t* a, const uint32_t* b) {
    asm volatile(
        "mma.sync.aligned.m16n8k8.row.col.f32.tf32.tf32.f32 "
        "{%0,%1,%2,%3}, {%4,%5,%6,%7}, {%8,%9}, {%0,%1,%2,%3};"
        : "+f"(d[0]), "+f"(d[1]), "+f"(d[2]), "+f"(d[3])
        : "r"(a[0]), "r"(a[1]), "r"(a[2]), "r"(a[3]), "r"(b[0]), "r"(b[1]));
}

// ---------------------------------------------------------------------------
// tf32 tensor-core GEMM: C[m][n] = sum_k A[m*lda+k]*B[n*ldb+k]
// CTA tile 128x128, BK=32, 8 warps (64x32 each), cp.async double-buffered.
// Requires M%128==0, K%32==0. N may have a tail (zero-filled B rows).
// ---------------------------------------------------------------------------
#define LDT 36
#define TILE_FLOATS (128 * LDT)
#define GEMM_SMEM_BYTES (4 * TILE_FLOATS * 4)   // 2 bufs x (A,B) = 73728 B

template<bool SOFTPLUS>
__global__ void __launch_bounds__(256) gemm_mma(
    const float* __restrict__ A, const float* __restrict__ B,
    const float* __restrict__ bias, float* __restrict__ C,
    int M, int N, int K, int lda, int ldb, int ldc)
{
    extern __shared__ float sm[];
    float* As = sm;                      // [2][128][LDT]
    float* Bs = sm + 2 * TILE_FLOATS;    // [2][128][LDT]

    const int tid  = threadIdx.x;
    const int wid  = tid >> 5, lane = tid & 31;
    const int g    = lane >> 2, tg = lane & 3;
    const int wm   = (wid >> 2) * 64;    // warp row origin within tile
    const int wn   = (wid & 3) * 32;     // warp col origin within tile
    const int m0   = blockIdx.y * 128, n0 = blockIdx.x * 128;

    // zero-fill B rows beyond N (tail tile) — those rows are never cp.async'd
    if (n0 + 128 > N) {
        int rstart = N - n0; if (rstart < 0) rstart = 0;
        for (int i = tid; i < 2 * TILE_FLOATS; i += 256) {
            int r = (i / LDT) & 127;
            if (r >= rstart) Bs[i] = 0.f;
        }
    }

    const int KT = K / 32;

    // tile loader: 1024 float4 per (A or B) tile, 4 per thread
    auto load_tiles = [&](int kt, int buf) {
        const float* Ab = A + (size_t)m0 * lda + kt * 32;
        const float* Bb = B + (size_t)n0 * ldb + kt * 32;
        float* Asb = As + buf * TILE_FLOATS;
        float* Bsb = Bs + buf * TILE_FLOATS;
#pragma unroll
        for (int i = 0; i < 4; ++i) {
            int f = tid + i * 256;
            int r = f >> 3, c = (f & 7) << 2;
            cpasync16(Asb + r * LDT + c, Ab + (size_t)r * lda + c);
            if (n0 + r < N)
                cpasync16(Bsb + r * LDT + c, Bb + (size_t)r * ldb + c);
        }
    };

    float acc[4][4][4];
#pragma unroll
    for (int i = 0; i < 4; ++i)
#pragma unroll
        for (int j = 0; j < 4; ++j)
#pragma unroll
            for (int r = 0; r < 4; ++r) acc[i][j][r] = 0.f;

    // prologue
    load_tiles(0, 0);
    asm volatile("cp.async.commit_group;");

    for (int kt = 0; kt < KT; ++kt) {
        if (kt + 1 < KT) {
            load_tiles(kt + 1, (kt + 1) & 1);
            asm volatile("cp.async.commit_group;");
            asm volatile("cp.async.wait_group 1;");
        } else {
            asm volatile("cp.async.wait_group 0;");
        }
        __syncthreads();

        const float* Asb = As + (kt & 1) * TILE_FLOATS;
        const float* Bsb = Bs + (kt & 1) * TILE_FLOATS;
#pragma unroll
        for (int ks = 0; ks < 4; ++ks) {
            const int k0 = ks * 8;
            uint32_t af[4][4], bf[4][2];
#pragma unroll
            for (int mi = 0; mi < 4; ++mi) {
                const float* p = Asb + (wm + mi * 16) * LDT + k0;
                af[mi][0] = f2tf(p[g * LDT + tg]);
                af[mi][1] = f2tf(p[(g + 8) * LDT + tg]);
                af[mi][2] = f2tf(p[g * LDT + tg + 4]);
                af[mi][3] = f2tf(p[(g + 8) * LDT + tg + 4]);
            }
#pragma unroll
            for (int ni = 0; ni < 4; ++ni) {
                const float* p = Bsb + (wn + ni * 8 + g) * LDT + k0;
                bf[ni][0] = f2tf(p[tg]);
                bf[ni][1] = f2tf(p[tg + 4]);
            }
#pragma unroll
            for (int mi = 0; mi < 4; ++mi)
#pragma unroll
                for (int ni = 0; ni < 4; ++ni)
                    mma_tf32(acc[mi][ni], af[mi], bf[ni]);
        }
        __syncthreads();
    }

    // epilogue
#pragma unroll
    for (int mi = 0; mi < 4; ++mi) {
        const int r0 = m0 + wm + mi * 16 + g;
#pragma unroll
        for (int ni = 0; ni < 4; ++ni) {
            const int col = n0 + wn + ni * 8 + 2 * tg;
            if (col >= N) continue;
            float v0 = acc[mi][ni][0], v1 = acc[mi][ni][1];
            float v2 = acc[mi][ni][2], v3 = acc[mi][ni][3];
            if (SOFTPLUS) {
                float b0 = bias[col], b1 = bias[col + 1];
                v0 += b0; v1 += b1; v2 += b0; v3 += b1;
                v0 = (v0 > 20.f) ? v0 : log1pf(expf(v0));
                v1 = (v1 > 20.f) ? v1 : log1pf(expf(v1));
                v2 = (v2 > 20.f) ? v2 : log1pf(expf(v2));
                v3 = (v3 > 20.f) ? v3 : log1pf(expf(v3));
            }
            *(float2*)&C[(size_t)r0 * ldc + col]       = make_float2(v0, v1);
            *(float2*)&C[(size_t)(r0 + 8) * ldc + col] = make_float2(v2, v3);
        }
    }
}

// ---------------------------------------------------------------------------
// Depthwise causal conv (4-tap) + SiLU
// ---------------------------------------------------------------------------
__global__ void conv_silu_kernel(const float* __restrict__ cw,
                                 const float* __restrict__ cb)
{
    int idx = blockIdx.x * blockDim.x + threadIdx.x;
    if (idx >= L_SEQ * DI) return;
    int l = idx / DI, d = idx % DI;
    float acc = cb[d];
#pragma unroll
    for (int t = 0; t < 4; ++t) {
        int ll = l - 3 + t;
        if (ll >= 0) acc = fmaf(cw[d * 4 + t], g_xz[(size_t)ll * (2 * DI) + d], acc);
    }
    g_xs[idx] = acc / (1.f + __expf(-acc));
}

// ---------------------------------------------------------------------------
// Selective scan: 16 lanes/channel, shfl-xor reduce; fuses +xs*D and *silu(z)
// ---------------------------------------------------------------------------
__global__ void __launch_bounds__(256) scan_kernel(
    const float* __restrict__ A_log, const float* __restrict__ Dp)
{
    const int d = blockIdx.x * 16 + (threadIdx.x >> 4);
    const int n = threadIdx.x & 15;
    const float a  = -__expf(A_log[d * DS + n]);
    const float Dd = Dp[d];
    float h = 0.f;
#pragma unroll 2
    for (int l = 0; l < L_SEQ; ++l) {
        float dt = g_dt[(size_t)l * DI + d];
        float xv = g_xs[(size_t)l * DI + d];
        float b  = g_xdbl[l * XDBL + DTR + n];
        float c  = g_xdbl[l * XDBL + DTR + DS + n];
        float dA = __expf(dt * a);
        h = fmaf(dA, h, dt * b * xv);
        float p = h * c;
        p += __shfl_xor_sync(0xffffffffu, p, 1);
        p += __shfl_xor_sync(0xffffffffu, p, 2);
        p += __shfl_xor_sync(0xffffffffu, p, 4);
        p += __shfl_xor_sync(0xffffffffu, p, 8);
        if (n == 0) {
            float z  = g_xz[(size_t)l * (2 * DI) + DI + d];
            float sz = z / (1.f + __expf(-z));
            g_y[(size_t)l * DI + d] = (p + xv * Dd) * sz;
        }
    }
}

// ---------------------------------------------------------------------------
extern "C" void kernel_launch(void* const* d_in, const int* in_sizes, int n_in,
                              void* d_out, int out_size)
{
    const float* x     = (const float*)d_in[0];
    const float* W_in  = (const float*)d_in[1];
    const float* cw    = (const float*)d_in[2];
    const float* cb    = (const float*)d_in[3];
    const float* W_x   = (const float*)d_in[4];
    const float* W_dt  = (const float*)d_in[5];
    const float* b_dt  = (const float*)d_in[6];
    const float* A_log = (const float*)d_in[7];
    const float* Dp    = (const float*)d_in[8];
    const float* W_out = (const float*)d_in[9];
    float* out = (float*)d_out;

    float *xz, *xs, *xdbl, *dt, *y;
    cudaGetSymbolAddress((void**)&xz,   g_xz);
    cudaGetSymbolAddress((void**)&xs,   g_xs);
    cudaGetSymbolAddress((void**)&xdbl, g_xdbl);
    cudaGetSymbolAddress((void**)&dt,   g_dt);
    cudaGetSymbolAddress((void**)&y,    g_y);

    cudaFuncSetAttribute(gemm_mma<false>,
        cudaFuncAttributeMaxDynamicSharedMemorySize, GEMM_SMEM_BYTES);
    cudaFuncSetAttribute(gemm_mma<true>,
        cudaFuncAttributeMaxDynamicSharedMemorySize, GEMM_SMEM_BYTES);

    // 1) xz = x @ W_in^T : (2048x1024)*(4096x1024)^T
    gemm_mma<false><<<dim3(4096 / 128, 2048 / 128), 256, GEMM_SMEM_BYTES>>>(
        x, W_in, nullptr, xz, L_SEQ, 2 * DI, DM, DM, DM, 2 * DI);

    // 2) conv + silu
    conv_silu_kernel<<<(L_SEQ * DI + 255) / 256, 256>>>(cw, cb);

    // 3) x_dbl = xs @ W_x^T : (2048x2048)*(96x2048)^T  (N tail)
    gemm_mma<false><<<dim3(1, 2048 / 128), 256, GEMM_SMEM_BYTES>>>(
        xs, W_x, nullptr, xdbl, L_SEQ, XDBL, DI, DI, DI, XDBL);

    // 4) dt = softplus(x_dbl[:, :64] @ W_dt^T + b_dt)
    gemm_mma<true><<<dim3(2048 / 128, 2048 / 128), 256, GEMM_SMEM_BYTES>>>(
        xdbl, W_dt, b_dt, dt, L_SEQ, DI, DTR, XDBL, DTR, DI);

    // 5) selective scan
    scan_kernel<<<DI / 16, 256>>>(A_log, Dp);

    // 6) out = y @ W_out^T : (2048x2048)*(1024x2048)^T
    gemm_mma<false><<<dim3(1024 / 128, 2048 / 128), 256, GEMM_SMEM_BYTES>>>(
        y, W_out, nullptr, out, L_SEQ, DM, DI, DI, DI, DM);
}

// round 5
// speedup vs baseline: 3.8330x; 2.8603x over previous
#include <cuda_runtime.h>
#include <cuda_fp16.h>
#include <math.h>
#include <stdint.h>

#define L_SEQ 2048
#define DM    1024
#define DI    2048
#define DS    16
#define DTR   64
#define XDBL  96

// float scratch
__device__ float g_xz[L_SEQ * 2 * DI];
__device__ float g_xs[L_SEQ * DI];
__device__ float g_xdbl[L_SEQ * XDBL];
__device__ float g_dt[L_SEQ * DI];
// half scratch
__device__ __half g_xh[L_SEQ * DM];
__device__ __half g_Winh[2 * DI * DM];
__device__ __half g_Wxh[XDBL * DI];
__device__ __half g_Wdth[DI * DTR];
__device__ __half g_Wouth[DM * DI];
__device__ __half g_xsh[L_SEQ * DI];
__device__ __half g_xdblh[L_SEQ * XDBL];
__device__ __half g_yh[L_SEQ * DI];

// ---------------------------------------------------------------------------
__device__ __forceinline__ void cpasync16(void* smem_ptr, const void* gptr) {
    uint32_t sa = (uint32_t)__cvta_generic_to_shared(smem_ptr);
    asm volatile("cp.async.cg.shared.global [%0], [%1], 16;" :: "r"(sa), "l"(gptr));
}
__device__ __forceinline__ void mma_f16(float* d, const uint32_t* a, const uint32_t* b) {
    asm volatile(
        "mma.sync.aligned.m16n8k16.row.col.f32.f16.f16.f32 "
        "{%0,%1,%2,%3}, {%4,%5,%6,%7}, {%8,%9}, {%0,%1,%2,%3};"
        : "+f"(d[0]), "+f"(d[1]), "+f"(d[2]), "+f"(d[3])
        : "r"(a[0]), "r"(a[1]), "r"(a[2]), "r"(a[3]), "r"(b[0]), "r"(b[1]));
}
__device__ __forceinline__ uint32_t lds32(const __half* p) {
    return *(const uint32_t*)p;
}

// ---------------------------------------------------------------------------
// float -> half (round-nearest), n even
// ---------------------------------------------------------------------------
__global__ void f2h_kernel(const float* __restrict__ src, __half* __restrict__ dst, int n)
{
    int i = (blockIdx.x * blockDim.x + threadIdx.x) * 2;
    if (i < n) {
        float2 v = *(const float2*)(src + i);
        *(__half2*)(dst + i) = __floats2half2_rn(v.x, v.y);
    }
}

// ---------------------------------------------------------------------------
// fp16 tensor-core GEMM: C[m][n] = sum_k A[m*lda+k]*B[n*ldb+k], f32 accum.
// CTA 128x128, BK=32, 8 warps (64x32), cp.async double-buffered, static smem.
// M%128==0, K%32==0; N may have tail (zero-filled B rows).
// ---------------------------------------------------------------------------
#define LDH 40

template<bool SOFTPLUS, bool WRITE_HALF>
__global__ void __launch_bounds__(256) gemm_h(
    const __half* __restrict__ A, const __half* __restrict__ B,
    const float* __restrict__ bias, float* __restrict__ C,
    __half* __restrict__ Ch,
    int M, int N, int K, int lda, int ldb, int ldc)
{
    __shared__ __align__(16) __half As[2][128][LDH];
    __shared__ __align__(16) __half Bs[2][128][LDH];

    const int tid  = threadIdx.x;
    const int wid  = tid >> 5, lane = tid & 31;
    const int g    = lane >> 2, tg = lane & 3;
    const int wm   = (wid >> 2) * 64;
    const int wn   = (wid & 3) * 32;
    const int m0   = blockIdx.y * 128, n0 = blockIdx.x * 128;

    // zero-fill B rows beyond N in both buffers (only data cols 0..31 matter)
    if (n0 + 128 > N) {
        int rstart = N - n0; if (rstart < 0) rstart = 0;
        for (int i = tid; i < 2 * 128 * (LDH / 2); i += 256) {
            int r = (i / (LDH / 2)) & 127;
            if (r >= rstart) ((uint32_t*)Bs)[i] = 0u;
        }
        __syncthreads();
    }

    const int KT = K / 32;

    auto load_tiles = [&](int kt, int buf) {
        const __half* Ab = A + (size_t)m0 * lda + kt * 32;
        const __half* Bb = B + (size_t)n0 * ldb + kt * 32;
#pragma unroll
        for (int i = 0; i < 2; ++i) {
            int f = tid + i * 256;          // 0..511
            int r = f >> 2, c = (f & 3) * 8;
            cpasync16(&As[buf][r][c], Ab + (size_t)r * lda + c);
            if (n0 + r < N)
                cpasync16(&Bs[buf][r][c], Bb + (size_t)r * ldb + c);
        }
    };

    float acc[4][4][4];
#pragma unroll
    for (int i = 0; i < 4; ++i)
#pragma unroll
        for (int j = 0; j < 4; ++j)
#pragma unroll
            for (int r = 0; r < 4; ++r) acc[i][j][r] = 0.f;

    load_tiles(0, 0);
    asm volatile("cp.async.commit_group;");

    for (int kt = 0; kt < KT; ++kt) {
        if (kt + 1 < KT) {
            load_tiles(kt + 1, (kt + 1) & 1);
            asm volatile("cp.async.commit_group;");
            asm volatile("cp.async.wait_group 1;");
        } else {
            asm volatile("cp.async.wait_group 0;");
        }
        __syncthreads();

        const int buf = kt & 1;
#pragma unroll
        for (int ks = 0; ks < 2; ++ks) {
            const int k0 = ks * 16;
            uint32_t af[4][4], bf[4][2];
#pragma unroll
            for (int mi = 0; mi < 4; ++mi) {
                const __half* p = &As[buf][wm + mi * 16][k0 + 2 * tg];
                af[mi][0] = lds32(p + g * LDH);
                af[mi][1] = lds32(p + (g + 8) * LDH);
                af[mi][2] = lds32(p + g * LDH + 8);
                af[mi][3] = lds32(p + (g + 8) * LDH + 8);
            }
#pragma unroll
            for (int ni = 0; ni < 4; ++ni) {
                const __half* q = &Bs[buf][wn + ni * 8 + g][k0 + 2 * tg];
                bf[ni][0] = lds32(q);
                bf[ni][1] = lds32(q + 8);
            }
#pragma unroll
            for (int mi = 0; mi < 4; ++mi)
#pragma unroll
                for (int ni = 0; ni < 4; ++ni)
                    mma_f16(acc[mi][ni], af[mi], bf[ni]);
        }
        __syncthreads();
    }

    // epilogue
#pragma unroll
    for (int mi = 0; mi < 4; ++mi) {
        const int r0 = m0 + wm + mi * 16 + g;
#pragma unroll
        for (int ni = 0; ni < 4; ++ni) {
            const int col = n0 + wn + ni * 8 + 2 * tg;
            if (col >= N) continue;
            float v0 = acc[mi][ni][0], v1 = acc[mi][ni][1];
            float v2 = acc[mi][ni][2], v3 = acc[mi][ni][3];
            if (SOFTPLUS) {
                float b0 = bias[col], b1 = bias[col + 1];
                v0 += b0; v1 += b1; v2 += b0; v3 += b1;
                v0 = (v0 > 20.f) ? v0 : log1pf(expf(v0));
                v1 = (v1 > 20.f) ? v1 : log1pf(expf(v1));
                v2 = (v2 > 20.f) ? v2 : log1pf(expf(v2));
                v3 = (v3 > 20.f) ? v3 : log1pf(expf(v3));
            }
            *(float2*)&C[(size_t)r0 * ldc + col]       = make_float2(v0, v1);
            *(float2*)&C[(size_t)(r0 + 8) * ldc + col] = make_float2(v2, v3);
            if (WRITE_HALF) {
                *(__half2*)&Ch[(size_t)r0 * ldc + col]       = __floats2half2_rn(v0, v1);
                *(__half2*)&Ch[(size_t)(r0 + 8) * ldc + col] = __floats2half2_rn(v2, v3);
            }
        }
    }
}

// ---------------------------------------------------------------------------
// Depthwise causal conv (4-tap) + SiLU -> float (scan) + half (GEMM)
// ---------------------------------------------------------------------------
__global__ void conv_silu_kernel(const float* __restrict__ cw,
                                 const float* __restrict__ cb)
{
    int idx = blockIdx.x * blockDim.x + threadIdx.x;
    if (idx >= L_SEQ * DI) return;
    int l = idx / DI, d = idx % DI;
    float acc = cb[d];
#pragma unroll
    for (int t = 0; t < 4; ++t) {
        int ll = l - 3 + t;
        if (ll >= 0) acc = fmaf(cw[d * 4 + t], g_xz[(size_t)ll * (2 * DI) + d], acc);
    }
    float s = acc / (1.f + __expf(-acc));
    g_xs[idx]  = s;
    g_xsh[idx] = __float2half_rn(s);
}

// ---------------------------------------------------------------------------
// Selective scan, depth-8 software-pipelined prefetch.
// 16 lanes/channel; fuses +xs*D and *silu(z); writes y as half.
// ---------------------------------------------------------------------------
#define PF 8
__global__ void __launch_bounds__(256) scan_kernel(
    const float* __restrict__ A_log, const float* __restrict__ Dp)
{
    const int d = blockIdx.x * 16 + (threadIdx.x >> 4);
    const int n = threadIdx.x & 15;
    const float a  = -__expf(A_log[d * DS + n]);
    const float Dd = Dp[d];
    const bool lead = (n == 0);

    float cdt[PF], cxv[PF], cb[PF], cc[PF], cz[PF];
#pragma unroll
    for (int j = 0; j < PF; ++j) {
        cdt[j] = g_dt[(size_t)j * DI + d];
        cxv[j] = g_xs[(size_t)j * DI + d];
        cb[j]  = g_xdbl[j * XDBL + DTR + n];
        cc[j]  = g_xdbl[j * XDBL + DTR + DS + n];
        cz[j]  = lead ? g_xz[(size_t)j * (2 * DI) + DI + d] : 0.f;
    }

    float h = 0.f;
    for (int l0 = 0; l0 < L_SEQ; l0 += PF) {
        float ndt[PF], nxv[PF], nb[PF], nc[PF], nz[PF];
        const bool more = (l0 + PF < L_SEQ);
        if (more) {
#pragma unroll
            for (int j = 0; j < PF; ++j) {
                int l = l0 + PF + j;
                ndt[j] = g_dt[(size_t)l * DI + d];
                nxv[j] = g_xs[(size_t)l * DI + d];
                nb[j]  = g_xdbl[l * XDBL + DTR + n];
                nc[j]  = g_xdbl[l * XDBL + DTR + DS + n];
                nz[j]  = lead ? g_xz[(size_t)l * (2 * DI) + DI + d] : 0.f;
            }
        }
#pragma unroll
        for (int j = 0; j < PF; ++j) {
            float dt = cdt[j], xv = cxv[j];
            float dA = __expf(dt * a);
            h = fmaf(dA, h, dt * cb[j] * xv);
            float p = h * cc[j];
            p += __shfl_xor_sync(0xffffffffu, p, 1);
            p += __shfl_xor_sync(0xffffffffu, p, 2);
            p += __shfl_xor_sync(0xffffffffu, p, 4);
            p += __shfl_xor_sync(0xffffffffu, p, 8);
            if (lead) {
                float z  = cz[j];
                float sz = z / (1.f + __expf(-z));
                g_yh[(size_t)(l0 + j) * DI + d] =
                    __float2half_rn((p + xv * Dd) * sz);
            }
        }
        if (more) {
#pragma unroll
            for (int j = 0; j < PF; ++j) {
                cdt[j] = ndt[j]; cxv[j] = nxv[j];
                cb[j] = nb[j]; cc[j] = nc[j]; cz[j] = nz[j];
            }
        }
    }
}

// ---------------------------------------------------------------------------
extern "C" void kernel_launch(void* const* d_in, const int* in_sizes, int n_in,
                              void* d_out, int out_size)
{
    const float* x     = (const float*)d_in[0];
    const float* W_in  = (const float*)d_in[1];
    const float* cw    = (const float*)d_in[2];
    const float* cb    = (const float*)d_in[3];
    const float* W_x   = (const float*)d_in[4];
    const float* W_dt  = (const float*)d_in[5];
    const float* b_dt  = (const float*)d_in[6];
    const float* A_log = (const float*)d_in[7];
    const float* Dp    = (const float*)d_in[8];
    const float* W_out = (const float*)d_in[9];
    float* out = (float*)d_out;

    float *xz, *xdbl, *dt;
    __half *xh, *Winh, *Wxh, *Wdth, *Wouth, *xsh, *xdblh, *yh;
    cudaGetSymbolAddress((void**)&xz,    g_xz);
    cudaGetSymbolAddress((void**)&xdbl,  g_xdbl);
    cudaGetSymbolAddress((void**)&dt,    g_dt);
    cudaGetSymbolAddress((void**)&xh,    g_xh);
    cudaGetSymbolAddress((void**)&Winh,  g_Winh);
    cudaGetSymbolAddress((void**)&Wxh,   g_Wxh);
    cudaGetSymbolAddress((void**)&Wdth,  g_Wdth);
    cudaGetSymbolAddress((void**)&Wouth, g_Wouth);
    cudaGetSymbolAddress((void**)&xsh,   g_xsh);
    cudaGetSymbolAddress((void**)&xdblh, g_xdblh);
    cudaGetSymbolAddress((void**)&yh,    g_yh);

    // 0) convert inputs to half
    const int CT = 256;
    f2h_kernel<<<(L_SEQ * DM / 2 + CT - 1) / CT, CT>>>(x, xh, L_SEQ * DM);
    f2h_kernel<<<(2 * DI * DM / 2 + CT - 1) / CT, CT>>>(W_in, Winh, 2 * DI * DM);
    f2h_kernel<<<(XDBL * DI / 2 + CT - 1) / CT, CT>>>(W_x, Wxh, XDBL * DI);
    f2h_kernel<<<(DI * DTR / 2 + CT - 1) / CT, CT>>>(W_dt, Wdth, DI * DTR);
    f2h_kernel<<<(DM * DI / 2 + CT - 1) / CT, CT>>>(W_out, Wouth, DM * DI);

    // 1) xz = x @ W_in^T : (2048x1024)*(4096x1024)^T -> f32
    gemm_h<false, false><<<dim3(4096 / 128, 2048 / 128), 256>>>(
        xh, Winh, nullptr, xz, nullptr, L_SEQ, 2 * DI, DM, DM, DM, 2 * DI);

    // 2) conv + silu -> xs (f32) + xsh (f16)
    conv_silu_kernel<<<(L_SEQ * DI + 255) / 256, 256>>>(cw, cb);

    // 3) x_dbl = xs @ W_x^T -> f32 + f16 copy (N=96 tail)
    gemm_h<false, true><<<dim3(1, 2048 / 128), 256>>>(
        xsh, Wxh, nullptr, xdbl, xdblh, L_SEQ, XDBL, DI, DI, DI, XDBL);

    // 4) dt = softplus(x_dbl[:, :64] @ W_dt^T + b_dt) -> f32
    gemm_h<true, false><<<dim3(2048 / 128, 2048 / 128), 256>>>(
        xdblh, Wdth, b_dt, dt, nullptr, L_SEQ, DI, DTR, XDBL, DTR, DI);

    // 5) selective scan -> yh (f16)
    scan_kernel<<<DI / 16, 256>>>(A_log, Dp);

    // 6) out = y @ W_out^T -> f32
    gemm_h<false, false><<<dim3(1024 / 128, 2048 / 128), 256>>>(
        yh, Wouth, nullptr, out, nullptr, L_SEQ, DM, DI, DI, DI, DM);
}

// round 6
// speedup vs baseline: 4.8875x; 1.2751x over previous
#include <cuda_runtime.h>
#include <cuda_fp16.h>
#include <math.h>
#include <stdint.h>

#define L_SEQ 2048
#define DM    1024
#define DI    2048
#define DS    16
#define DTR   64
#define XDBL  96
#define NCH   8
#define CL    (L_SEQ / NCH)   // 256

// float scratch
__device__ float g_xz[L_SEQ * 2 * DI];
__device__ float g_xs[L_SEQ * DI];
__device__ float g_xdbl[L_SEQ * XDBL];
__device__ float g_dt[L_SEQ * DI];
// chunked-scan scratch
__device__ float g_P[NCH * DI * DS];
__device__ float g_q[NCH * DI * DS];
__device__ float g_hin[NCH * DI * DS];
// half scratch
__device__ __half g_xh[L_SEQ * DM];
__device__ __half g_Winh[2 * DI * DM];
__device__ __half g_Wxh[XDBL * DI];
__device__ __half g_Wdth[DI * DTR];
__device__ __half g_Wouth[DM * DI];
__device__ __half g_xsh[L_SEQ * DI];
__device__ __half g_xdblh[L_SEQ * XDBL];
__device__ __half g_yh[L_SEQ * DI];

// ---------------------------------------------------------------------------
__device__ __forceinline__ void cpasync16(void* smem_ptr, const void* gptr) {
    uint32_t sa = (uint32_t)__cvta_generic_to_shared(smem_ptr);
    asm volatile("cp.async.cg.shared.global [%0], [%1], 16;" :: "r"(sa), "l"(gptr));
}
__device__ __forceinline__ void mma_f16(float* d, const uint32_t* a, const uint32_t* b) {
    asm volatile(
        "mma.sync.aligned.m16n8k16.row.col.f32.f16.f16.f32 "
        "{%0,%1,%2,%3}, {%4,%5,%6,%7}, {%8,%9}, {%0,%1,%2,%3};"
        : "+f"(d[0]), "+f"(d[1]), "+f"(d[2]), "+f"(d[3])
        : "r"(a[0]), "r"(a[1]), "r"(a[2]), "r"(a[3]), "r"(b[0]), "r"(b[1]));
}
__device__ __forceinline__ void ldsm_x4(uint32_t& r0, uint32_t& r1,
                                        uint32_t& r2, uint32_t& r3, uint32_t addr) {
    asm volatile("ldmatrix.sync.aligned.m8n8.x4.shared.b16 {%0,%1,%2,%3}, [%4];"
                 : "=r"(r0), "=r"(r1), "=r"(r2), "=r"(r3) : "r"(addr));
}

// ---------------------------------------------------------------------------
// float -> half, 4 elems/thread
// ---------------------------------------------------------------------------
__global__ void f2h_kernel(const float4* __restrict__ src, uint2* __restrict__ dst, int n4)
{
    int i = blockIdx.x * blockDim.x + threadIdx.x;
    if (i < n4) {
        float4 v = src[i];
        __half2 h0 = __floats2half2_rn(v.x, v.y);
        __half2 h1 = __floats2half2_rn(v.z, v.w);
        dst[i] = make_uint2(*(uint32_t*)&h0, *(uint32_t*)&h1);
    }
}

// ---------------------------------------------------------------------------
// fp16 tensor-core GEMM, ldmatrix fragment loads.
// CTA 128x128, BK=32, 8 warps (64x32), cp.async double-buffered.
// M%128==0, K%32==0; N may have tail (zero-filled B rows).
// ---------------------------------------------------------------------------
#define LDH 40

template<bool SOFTPLUS, bool WRITE_HALF>
__global__ void __launch_bounds__(256) gemm_h(
    const __half* __restrict__ A, const __half* __restrict__ B,
    const float* __restrict__ bias, float* __restrict__ C,
    __half* __restrict__ Ch,
    int M, int N, int K, int lda, int ldb, int ldc)
{
    __shared__ __align__(16) __half As[2][128][LDH];
    __shared__ __align__(16) __half Bs[2][128][LDH];

    const int tid  = threadIdx.x;
    const int wid  = tid >> 5, lane = tid & 31;
    const int g    = lane >> 2, tg = lane & 3;
    const int wm   = (wid >> 2) * 64;
    const int wn   = (wid & 3) * 32;
    const int m0   = blockIdx.y * 128, n0 = blockIdx.x * 128;

    // ldmatrix per-lane offset (bytes): row (lane&7)+((lane>>3)&1)*8, col (lane>>4)*8
    const int lm_row = (lane & 7) + ((lane >> 3) & 1) * 8;
    const int lm_col = (lane >> 4) * 8;
    const uint32_t lm_off = (uint32_t)(lm_row * LDH + lm_col) * 2;
    const uint32_t as_base = (uint32_t)__cvta_generic_to_shared(&As[0][0][0]);
    const uint32_t bs_base = (uint32_t)__cvta_generic_to_shared(&Bs[0][0][0]);
    const uint32_t tile_bytes = 128 * LDH * 2;

    if (n0 + 128 > N) {
        int rstart = N - n0; if (rstart < 0) rstart = 0;
        for (int i = tid; i < 2 * 128 * (LDH / 2); i += 256) {
            int r = (i / (LDH / 2)) & 127;
            if (r >= rstart) ((uint32_t*)Bs)[i] = 0u;
        }
        __syncthreads();
    }

    const int KT = K / 32;

    auto load_tiles = [&](int kt, int buf) {
        const __half* Ab = A + (size_t)m0 * lda + kt * 32;
        const __half* Bb = B + (size_t)n0 * ldb + kt * 32;
#pragma unroll
        for (int i = 0; i < 2; ++i) {
            int f = tid + i * 256;
            int r = f >> 2, c = (f & 3) * 8;
            cpasync16(&As[buf][r][c], Ab + (size_t)r * lda + c);
            if (n0 + r < N)
                cpasync16(&Bs[buf][r][c], Bb + (size_t)r * ldb + c);
        }
    };

    float acc[4][4][4];
#pragma unroll
    for (int i = 0; i < 4; ++i)
#pragma unroll
        for (int j = 0; j < 4; ++j)
#pragma unroll
            for (int r = 0; r < 4; ++r) acc[i][j][r] = 0.f;

    load_tiles(0, 0);
    asm volatile("cp.async.commit_group;");

    for (int kt = 0; kt < KT; ++kt) {
        if (kt + 1 < KT) {
            load_tiles(kt + 1, (kt + 1) & 1);
            asm volatile("cp.async.commit_group;");
            asm volatile("cp.async.wait_group 1;");
        } else {
            asm volatile("cp.async.wait_group 0;");
        }
        __syncthreads();

        const int buf = kt & 1;
        const uint32_t abuf = as_base + buf * tile_bytes + lm_off;
        const uint32_t bbuf = bs_base + buf * tile_bytes + lm_off;
#pragma unroll
        for (int ks = 0; ks < 2; ++ks) {
            const uint32_t k0b = (uint32_t)(ks * 16) * 2;
            uint32_t af[4][4], bf[4][2];
#pragma unroll
            for (int mi = 0; mi < 4; ++mi)
                ldsm_x4(af[mi][0], af[mi][1], af[mi][2], af[mi][3],
                        abuf + (uint32_t)((wm + mi * 16) * LDH) * 2 + k0b);
#pragma unroll
            for (int p = 0; p < 2; ++p)
                ldsm_x4(bf[2 * p][0], bf[2 * p + 1][0], bf[2 * p][1], bf[2 * p + 1][1],
                        bbuf + (uint32_t)((wn + p * 16) * LDH) * 2 + k0b);
#pragma unroll
            for (int mi = 0; mi < 4; ++mi)
#pragma unroll
                for (int ni = 0; ni < 4; ++ni)
                    mma_f16(acc[mi][ni], af[mi], bf[ni]);
        }
        __syncthreads();
    }

    // epilogue
#pragma unroll
    for (int mi = 0; mi < 4; ++mi) {
        const int r0 = m0 + wm + mi * 16 + g;
#pragma unroll
        for (int ni = 0; ni < 4; ++ni) {
            const int col = n0 + wn + ni * 8 + 2 * tg;
            if (col >= N) continue;
            float v0 = acc[mi][ni][0], v1 = acc[mi][ni][1];
            float v2 = acc[mi][ni][2], v3 = acc[mi][ni][3];
            if (SOFTPLUS) {
                float b0 = bias[col], b1 = bias[col + 1];
                v0 += b0; v1 += b1; v2 += b0; v3 += b1;
                v0 = (v0 > 20.f) ? v0 : log1pf(expf(v0));
                v1 = (v1 > 20.f) ? v1 : log1pf(expf(v1));
                v2 = (v2 > 20.f) ? v2 : log1pf(expf(v2));
                v3 = (v3 > 20.f) ? v3 : log1pf(expf(v3));
            }
            *(float2*)&C[(size_t)r0 * ldc + col]       = make_float2(v0, v1);
            *(float2*)&C[(size_t)(r0 + 8) * ldc + col] = make_float2(v2, v3);
            if (WRITE_HALF) {
                *(__half2*)&Ch[(size_t)r0 * ldc + col]       = __floats2half2_rn(v0, v1);
                *(__half2*)&Ch[(size_t)(r0 + 8) * ldc + col] = __floats2half2_rn(v2, v3);
            }
        }
    }
}

// ---------------------------------------------------------------------------
// Depthwise causal conv (4-tap) + SiLU -> float (scan) + half (GEMM)
// ---------------------------------------------------------------------------
__global__ void conv_silu_kernel(const float* __restrict__ cw,
                                 const float* __restrict__ cb)
{
    int idx = blockIdx.x * blockDim.x + threadIdx.x;
    if (idx >= L_SEQ * DI) return;
    int l = idx / DI, d = idx % DI;
    float acc = cb[d];
#pragma unroll
    for (int t = 0; t < 4; ++t) {
        int ll = l - 3 + t;
        if (ll >= 0) acc = fmaf(cw[d * 4 + t], g_xz[(size_t)ll * (2 * DI) + d], acc);
    }
    float s = acc / (1.f + __expf(-acc));
    g_xs[idx]  = s;
    g_xsh[idx] = __float2half_rn(s);
}

// ---------------------------------------------------------------------------
// Chunked selective scan.
// Pass 1: per chunk (c<NCH-1), compute q = scan(h_in=0) final h, P = prod(dA).
// Pass 2: combine chains across chunks -> h at chunk starts.
// Pass 3: per chunk, full scan from h_in with y output.
// ---------------------------------------------------------------------------
#define PF 8
__global__ void __launch_bounds__(256) scan_part1(const float* __restrict__ A_log)
{
    const int d = blockIdx.x * 16 + (threadIdx.x >> 4);
    const int n = threadIdx.x & 15;
    const int c = blockIdx.y;
    const float a = -__expf(A_log[d * DS + n]);
    const int lbase = c * CL;

    float cdt[PF], cxv[PF], cb[PF];
#pragma unroll
    for (int j = 0; j < PF; ++j) {
        int l = lbase + j;
        cdt[j] = g_dt[(size_t)l * DI + d];
        cxv[j] = g_xs[(size_t)l * DI + d];
        cb[j]  = g_xdbl[l * XDBL + DTR + n];
    }

    float h = 0.f, P = 1.f;
    for (int l0 = 0; l0 < CL; l0 += PF) {
        float ndt[PF], nxv[PF], nb[PF];
        const bool more = (l0 + PF < CL);
        if (more) {
#pragma unroll
            for (int j = 0; j < PF; ++j) {
                int l = lbase + l0 + PF + j;
                ndt[j] = g_dt[(size_t)l * DI + d];
                nxv[j] = g_xs[(size_t)l * DI + d];
                nb[j]  = g_xdbl[l * XDBL + DTR + n];
            }
        }
#pragma unroll
        for (int j = 0; j < PF; ++j) {
            float dA = __expf(cdt[j] * a);
            h = fmaf(dA, h, cdt[j] * cb[j] * cxv[j]);
            P *= dA;
        }
        if (more) {
#pragma unroll
            for (int j = 0; j < PF; ++j) { cdt[j] = ndt[j]; cxv[j] = nxv[j]; cb[j] = nb[j]; }
        }
    }
    g_q[((size_t)c * DI + d) * DS + n] = h;
    g_P[((size_t)c * DI + d) * DS + n] = P;
}

__global__ void __launch_bounds__(256) scan_combine()
{
    int idx = blockIdx.x * blockDim.x + threadIdx.x;  // (d,n) flat, DI*DS
    if (idx >= DI * DS) return;
    float hin = 0.f;
    g_hin[idx] = 0.f;
#pragma unroll
    for (int c = 0; c < NCH - 1; ++c) {
        hin = fmaf(g_P[(size_t)c * DI * DS + idx], hin, g_q[(size_t)c * DI * DS + idx]);
        g_hin[(size_t)(c + 1) * DI * DS + idx] = hin;
    }
}

__global__ void __launch_bounds__(256) scan_part2(
    const float* __restrict__ A_log, const float* __restrict__ Dp)
{
    const int d = blockIdx.x * 16 + (threadIdx.x >> 4);
    const int n = threadIdx.x & 15;
    const int c = blockIdx.y;
    const float a  = -__expf(A_log[d * DS + n]);
    const float Dd = Dp[d];
    const bool lead = (n == 0);
    const int lbase = c * CL;

    float cdt[PF], cxv[PF], cb[PF], cc[PF], cz[PF];
#pragma unroll
    for (int j = 0; j < PF; ++j) {
        int l = lbase + j;
        cdt[j] = g_dt[(size_t)l * DI + d];
        cxv[j] = g_xs[(size_t)l * DI + d];
        cb[j]  = g_xdbl[l * XDBL + DTR + n];
        cc[j]  = g_xdbl[l * XDBL + DTR + DS + n];
        cz[j]  = lead ? g_xz[(size_t)l * (2 * DI) + DI + d] : 0.f;
    }

    float h = g_hin[((size_t)c * DI + d) * DS + n];
    for (int l0 = 0; l0 < CL; l0 += PF) {
        float ndt[PF], nxv[PF], nb[PF], nc[PF], nz[PF];
        const bool more = (l0 + PF < CL);
        if (more) {
#pragma unroll
            for (int j = 0; j < PF; ++j) {
                int l = lbase + l0 + PF + j;
                ndt[j] = g_dt[(size_t)l * DI + d];
                nxv[j] = g_xs[(size_t)l * DI + d];
                nb[j]  = g_xdbl[l * XDBL + DTR + n];
                nc[j]  = g_xdbl[l * XDBL + DTR + DS + n];
                nz[j]  = lead ? g_xz[(size_t)l * (2 * DI) + DI + d] : 0.f;
            }
        }
#pragma unroll
        for (int j = 0; j < PF; ++j) {
            float dt = cdt[j], xv = cxv[j];
            float dA = __expf(dt * a);
            h = fmaf(dA, h, dt * cb[j] * xv);
            float p = h * cc[j];
            p += __shfl_xor_sync(0xffffffffu, p, 1);
            p += __shfl_xor_sync(0xffffffffu, p, 2);
            p += __shfl_xor_sync(0xffffffffu, p, 4);
            p += __shfl_xor_sync(0xffffffffu, p, 8);
            if (lead) {
                float z  = cz[j];
                float sz = z / (1.f + __expf(-z));
                g_yh[(size_t)(lbase + l0 + j) * DI + d] =
                    __float2half_rn((p + xv * Dd) * sz);
            }
        }
        if (more) {
#pragma unroll
            for (int j = 0; j < PF; ++j) {
                cdt[j] = ndt[j]; cxv[j] = nxv[j];
                cb[j] = nb[j]; cc[j] = nc[j]; cz[j] = nz[j];
            }
        }
    }
}

// ---------------------------------------------------------------------------
extern "C" void kernel_launch(void* const* d_in, const int* in_sizes, int n_in,
                              void* d_out, int out_size)
{
    const float* x     = (const float*)d_in[0];
    const float* W_in  = (const float*)d_in[1];
    const float* cw    = (const float*)d_in[2];
    const float* cb    = (const float*)d_in[3];
    const float* W_x   = (const float*)d_in[4];
    const float* W_dt  = (const float*)d_in[5];
    const float* b_dt  = (const float*)d_in[6];
    const float* A_log = (const float*)d_in[7];
    const float* Dp    = (const float*)d_in[8];
    const float* W_out = (const float*)d_in[9];
    float* out = (float*)d_out;

    float *xz, *xdbl, *dt;
    __half *xh, *Winh, *Wxh, *Wdth, *Wouth, *xsh, *xdblh, *yh;
    cudaGetSymbolAddress((void**)&xz,    g_xz);
    cudaGetSymbolAddress((void**)&xdbl,  g_xdbl);
    cudaGetSymbolAddress((void**)&dt,    g_dt);
    cudaGetSymbolAddress((void**)&xh,    g_xh);
    cudaGetSymbolAddress((void**)&Winh,  g_Winh);
    cudaGetSymbolAddress((void**)&Wxh,   g_Wxh);
    cudaGetSymbolAddress((void**)&Wdth,  g_Wdth);
    cudaGetSymbolAddress((void**)&Wouth, g_Wouth);
    cudaGetSymbolAddress((void**)&xsh,   g_xsh);
    cudaGetSymbolAddress((void**)&xdblh, g_xdblh);
    cudaGetSymbolAddress((void**)&yh,    g_yh);

    // 0) convert inputs to half (4 elems/thread)
    const int CT = 256;
    f2h_kernel<<<(L_SEQ * DM / 4 + CT - 1) / CT, CT>>>((const float4*)x, (uint2*)xh, L_SEQ * DM / 4);
    f2h_kernel<<<(2 * DI * DM / 4 + CT - 1) / CT, CT>>>((const float4*)W_in, (uint2*)Winh, 2 * DI * DM / 4);
    f2h_kernel<<<(XDBL * DI / 4 + CT - 1) / CT, CT>>>((const float4*)W_x, (uint2*)Wxh, XDBL * DI / 4);
    f2h_kernel<<<(DI * DTR / 4 + CT - 1) / CT, CT>>>((const float4*)W_dt, (uint2*)Wdth, DI * DTR / 4);
    f2h_kernel<<<(DM * DI / 4 + CT - 1) / CT, CT>>>((const float4*)W_out, (uint2*)Wouth, DM * DI / 4);

    // 1) xz = x @ W_in^T
    gemm_h<false, false><<<dim3(4096 / 128, 2048 / 128), 256>>>(
        xh, Winh, nullptr, xz, nullptr, L_SEQ, 2 * DI, DM, DM, DM, 2 * DI);

    // 2) conv + silu
    conv_silu_kernel<<<(L_SEQ * DI + 255) / 256, 256>>>(cw, cb);

    // 3) x_dbl = xs @ W_x^T (N=96 tail)
    gemm_h<false, true><<<dim3(1, 2048 / 128), 256>>>(
        xsh, Wxh, nullptr, xdbl, xdblh, L_SEQ, XDBL, DI, DI, DI, XDBL);

    // 4) dt = softplus(x_dbl[:, :64] @ W_dt^T + b_dt)
    gemm_h<true, false><<<dim3(2048 / 128, 2048 / 128), 256>>>(
        xdblh, Wdth, b_dt, dt, nullptr, L_SEQ, DI, DTR, XDBL, DTR, DI);

    // 5) chunked selective scan
    scan_part1<<<dim3(DI / 16, NCH - 1), 256>>>(A_log);
    scan_combine<<<(DI * DS + 255) / 256, 256>>>();
    scan_part2<<<dim3(DI / 16, NCH), 256>>>(A_log, Dp);

    // 6) out = y @ W_out^T
    gemm_h<false, false><<<dim3(1024 / 128, 2048 / 128), 256>>>(
        yh, Wouth, nullptr, out, nullptr, L_SEQ, DM, DI, DI, DI, DM);
}